// round 13
// baseline (speedup 1.0000x reference)
#include <cuda_runtime.h>
#include <cuda_fp16.h>
#include <cstdint>
#include <math.h>

#define LL 256
#define DD 128
#define NHEAD 4
#define DHEAD 32
#define NROWS (LL*LL)   // 65536
#define WST 68          // packed-pair row stride (uint32) for PN/att smem images

// ---------------- scratch ----------------
// fragment-major weights: g_Wf[p][(nf*8+ks)*32+lane] = uint2{b0,b1} mma B-operands
__device__ uint2    g_Wf[5][4096];
__device__ uint32_t g_qH[(size_t)NROWS*64];   // q pre-scaled by log2e/sqrt(32), fp16 split hi
__device__ uint32_t g_qL[(size_t)NROWS*64];   // fp16 split lo
__device__ uint32_t g_kH[(size_t)NROWS*64];   // k single fp16 pairs
__device__ uint32_t g_vTH[(size_t)LL*NHEAD*DHEAD*128];  // v^T single fp16 pairs [i][h][d][j-pair]
__device__ float    g_gate[(size_t)NROWS*DD];
__device__ uint32_t g_attH[(size_t)NROWS*64]; // att fp16 split hi
__device__ uint32_t g_attL[(size_t)NROWS*64]; // fp16 split lo
__device__ unsigned g_mask[LL*8];

// ---------------- helpers ----------------
__device__ __forceinline__ uint32_t packh(__half a, __half b){
    __half2 t; t.x = a; t.y = b;
    return *reinterpret_cast<uint32_t*>(&t);
}
__device__ __forceinline__ uint32_t pack1h(float x0, float x1){
    return packh(__float2half_rn(x0), __float2half_rn(x1));
}
__device__ __forceinline__ void split2h(float x0, float x1, uint32_t& hi, uint32_t& lo){
    __half h0 = __float2half_rn(x0);
    __half h1 = __float2half_rn(x1);
    __half l0 = __float2half_rn(x0 - __half2float(h0));
    __half l1 = __float2half_rn(x1 - __half2float(h1));
    hi = packh(h0, h1); lo = packh(l0, l1);
}
__device__ __forceinline__ void split1h(float x, __half& h, __half& l){
    h = __float2half_rn(x);
    l = __float2half_rn(x - __half2float(h));
}
__device__ __forceinline__ void mma16816(float* c, const uint32_t* a, uint32_t b0, uint32_t b1){
    asm volatile("mma.sync.aligned.m16n8k16.row.col.f32.f16.f16.f32 "
        "{%0,%1,%2,%3}, {%4,%5,%6,%7}, {%8,%9}, {%0,%1,%2,%3};\n"
        : "+f"(c[0]), "+f"(c[1]), "+f"(c[2]), "+f"(c[3])
        : "r"(a[0]), "r"(a[1]), "r"(a[2]), "r"(a[3]), "r"(b0), "r"(b1));
}
__device__ __forceinline__ uint32_t smaddr(const void* p){
    return (uint32_t)__cvta_generic_to_shared(p);
}
__device__ __forceinline__ void ldsm4(uint32_t* r, uint32_t a){
    asm volatile("ldmatrix.sync.aligned.m8n8.x4.shared.b16 {%0,%1,%2,%3}, [%4];"
        : "=r"(r[0]), "=r"(r[1]), "=r"(r[2]), "=r"(r[3]) : "r"(a));
}

// ---------------- kernel: prep weights into fragment-major table ----------------
__global__ void k_prep(const float* __restrict__ Wq, const float* __restrict__ Wk,
                       const float* __restrict__ Wv, const float* __restrict__ Wg,
                       const float* __restrict__ Wo)
{
    int m = blockIdx.x;
    const float* W = (m==0)?Wq:(m==1)?Wk:(m==2)?Wv:(m==3)?Wg:Wo;
    for (int idx = threadIdx.x; idx < 4096; idx += blockDim.x){
        int lane = idx & 31;
        int ks = (idx >> 5) & 7;
        int nf = idx >> 8;
        int e = nf*8 + (lane >> 2);
        int tig = lane & 3;
        int pd0 = ks*8 + tig, pd1 = pd0 + 4;
        uint2 v;
        v.x = pack1h(W[e*DD + 2*pd0], W[e*DD + 2*pd0 + 1]);
        v.y = pack1h(W[e*DD + 2*pd1], W[e*DD + 2*pd1 + 1]);
        g_Wf[m][idx] = v;
    }
}

// ---------------- kernel: pack mask ----------------
__global__ void k_maskpack(const int* __restrict__ mask)
{
    int j = threadIdx.x;
    const int* mrow = mask + (size_t)j*LL;
    #pragma unroll
    for (int w = 0; w < 8; w++){
        unsigned bits = 0;
        #pragma unroll
        for (int b = 0; b < 32; b++) bits |= (mrow[w*32+b] != 0 ? 1u : 0u) << b;
        g_mask[j*8 + w] = bits;
    }
}

// ---------------- kernel 1: LayerNorm + q/k/v/gate projections ----------------
// 256 threads, 64 rows/block. smem: PN hi/lo [64][68] = 34.8KB. Weights via LDG.
__global__ __launch_bounds__(256,3) void k_lnproj(
    const float* __restrict__ pair,
    const float* __restrict__ ln_g, const float* __restrict__ ln_b,
    const float* __restrict__ bq, const float* __restrict__ bk,
    const float* __restrict__ bv, const float* __restrict__ bg)
{
    extern __shared__ uint32_t sm[];
    uint32_t* PNH = sm;                 // 64*68
    uint32_t* PNL = sm + 64*WST;
    __half* PNHh = (__half*)PNH;
    __half* PNLh = (__half*)PNL;

    const int row0 = blockIdx.x * 64;
    const int tid = threadIdx.x;
    const int lane = tid & 31, wid = tid >> 5;
    const int gid = lane >> 2, tig = lane & 3;
    const int li = lane & 7, gb = lane >> 3;
    const float QSC = 0.17677669529663687f * 1.4426950408889634f;  // (1/sqrt 32)*log2(e)

    // ---- LayerNorm: 8 warps x 8 rows, fp16 split into smem ----
    {
        float lg[4], lb[4];
        #pragma unroll
        for (int t = 0; t < 4; t++){ lg[t] = ln_g[lane + 32*t]; lb[t] = ln_b[lane + 32*t]; }
        for (int rr = 0; rr < 8; rr++){
            int r = wid*8 + rr;
            const float* x = pair + (size_t)(row0 + r)*DD;
            float v[4];
            #pragma unroll
            for (int t = 0; t < 4; t++) v[t] = x[lane + 32*t];
            float s = v[0]+v[1]+v[2]+v[3];
            #pragma unroll
            for (int o = 16; o > 0; o >>= 1) s += __shfl_xor_sync(0xffffffffu, s, o);
            float mu = s * (1.f/128.f);
            float sq = 0.f;
            #pragma unroll
            for (int t = 0; t < 4; t++){ v[t] -= mu; sq += v[t]*v[t]; }
            #pragma unroll
            for (int o = 16; o > 0; o >>= 1) sq += __shfl_xor_sync(0xffffffffu, sq, o);
            float rstd = rsqrtf(sq*(1.f/128.f) + 1e-5f);
            #pragma unroll
            for (int t = 0; t < 4; t++){
                float pn = v[t]*rstd*lg[t] + lb[t];
                __half h, l; split1h(pn, h, l);
                PNHh[r*(2*WST) + lane + 32*t] = h;
                PNLh[r*(2*WST) + lane + 32*t] = l;
            }
        }
    }
    __syncthreads();

    const int wm = wid >> 2, wn = wid & 3;
    const int m0 = wm*32, n0 = wn*32;

    // ldmatrix per-lane bases (A side)
    const uint32_t aOff = ((uint32_t)(m0 + (gb&1)*8 + li)*WST + (gb>>1)*4) * 4;
    const uint32_t aH0 = smaddr(PNH) + aOff;
    const uint32_t aL0 = smaddr(PNL) + aOff;

    // projection order: q(0), k(1), gate(3), v(2) — PN must stay live until v (last)
    #pragma unroll
    for (int pi = 0; pi < 4; pi++){
        const int p = (pi==2) ? 3 : (pi==3) ? 2 : pi;
        const bool full = (p != 3);   // gate projection: 1-term
        const uint2* Wf = g_Wf[p] + (size_t)(wn*4)*8*32 + lane;

        float C[2][4][4];
        #pragma unroll
        for (int mi=0; mi<2; mi++)
            #pragma unroll
            for (int nf=0; nf<4; nf++)
                #pragma unroll
                for (int q=0; q<4; q++) C[mi][nf][q] = 0.f;

        #pragma unroll
        for (int ks = 0; ks < 8; ks++){
            uint32_t AH[2][4], AL[2][4];
            #pragma unroll
            for (int mi = 0; mi < 2; mi++){
                uint32_t o = (uint32_t)(mi*16*WST + ks*8) * 4;
                ldsm4(AH[mi], aH0 + o);
                if (full) ldsm4(AL[mi], aL0 + o);
            }
            #pragma unroll
            for (int nf = 0; nf < 4; nf++){
                uint2 B = Wf[(nf*8 + ks)*32];
                #pragma unroll
                for (int mi = 0; mi < 2; mi++){
                    mma16816(C[mi][nf], AH[mi], B.x, B.y);
                    if (full) mma16816(C[mi][nf], AL[mi], B.x, B.y);
                }
            }
        }

        if (p == 2) __syncthreads();   // v is last: all warps done reading PN before vt overlay

        const float* bias = (p==0)?bq:(p==1)?bk:(p==2)?bv:bg;
        #pragma unroll
        for (int mi = 0; mi < 2; mi++){
            #pragma unroll
            for (int nf = 0; nf < 4; nf++){
                int col = n0 + nf*8 + 2*tig;
                float b0 = bias[col], b1 = bias[col+1];
                float v00 = C[mi][nf][0] + b0, v01 = C[mi][nf][1] + b1;
                float v10 = C[mi][nf][2] + b0, v11 = C[mi][nf][3] + b1;
                int rl = m0 + mi*16 + gid;        // local row 0..63
                int r0 = row0 + rl;
                if (p == 0){
                    v00 *= QSC; v01 *= QSC; v10 *= QSC; v11 *= QSC;
                    uint32_t hi, lo;
                    split2h(v00, v01, hi, lo);
                    g_qH[(size_t)r0*64 + (col>>1)] = hi; g_qL[(size_t)r0*64 + (col>>1)] = lo;
                    split2h(v10, v11, hi, lo);
                    g_qH[(size_t)(r0+8)*64 + (col>>1)] = hi; g_qL[(size_t)(r0+8)*64 + (col>>1)] = lo;
                } else if (p == 1){
                    g_kH[(size_t)r0*64 + (col>>1)]     = pack1h(v00, v01);
                    g_kH[(size_t)(r0+8)*64 + (col>>1)] = pack1h(v10, v11);
                } else if (p == 2){
                    float* vt = (float*)sm;       // [64][131] overlay on PN region
                    vt[rl*131 + col] = v00; vt[rl*131 + col + 1] = v01;
                    vt[(rl+8)*131 + col] = v10; vt[(rl+8)*131 + col + 1] = v11;
                } else {
                    v00 = 1.f/(1.f+__expf(-v00)); v01 = 1.f/(1.f+__expf(-v01));
                    v10 = 1.f/(1.f+__expf(-v10)); v11 = 1.f/(1.f+__expf(-v11));
                    *(float2*)(g_gate + (size_t)r0*DD + col)     = make_float2(v00, v01);
                    *(float2*)(g_gate + (size_t)(r0+8)*DD + col) = make_float2(v10, v11);
                }
            }
        }
    }

    __syncthreads();
    // transpose v tile -> g_vTH (single fp16) (block covers j0..j0+63 of row i)
    {
        const int i_ = row0 >> 8, j0_ = row0 & 255;
        const float* vt = (const float*)sm;
        for (int idx = tid; idx < 4096; idx += 256){
            int h_ = idx >> 10;
            int rem = idx & 1023;
            int d_ = rem >> 5;
            int jp = rem & 31;
            float v0 = vt[(jp*2)*131 + h_*32 + d_];
            float v1 = vt[(jp*2+1)*131 + h_*32 + d_];
            size_t o = ((size_t)((i_*NHEAD + h_)*DHEAD + d_))*128 + (j0_>>1) + jp;
            g_vTH[o] = pack1h(v0, v1);
        }
    }
}

// ---------------- kernel 2: attention per (i,h,half) ----------------
// 256 threads / 8 warps, each warp owns 16 query rows. 2 blocks per (i,h).
// fp16 2-term: Q split (A), K single (B); P split (A), V single (B). ldmatrix B loads.
// smem (uint32): KH[256][20], VTH[32][132] = 37.4KB
#define AKH 0
#define AVH 5120
#define ATOT 9344
__global__ __launch_bounds__(256,2) void k_attn()
{
    extern __shared__ uint32_t sm[];
    uint32_t* KH = sm + AKH;    // [256][20]
    uint32_t* VTH = sm + AVH;   // [32][132]

    const int i = blockIdx.x, h = blockIdx.y, half = blockIdx.z;
    const int tid = threadIdx.x;
    const int lane = tid & 31, wid = tid >> 5;
    const int gid = lane >> 2, tig = lane & 3;
    const int li = lane & 7, gb = lane >> 3;

    // stage K and V^T (pure copies of fp16-packed data)
    {
        const uint4* kH4 = (const uint4*)g_kH;
        for (int idx = tid; idx < 1024; idx += 256){
            int r = idx >> 2, c4 = idx & 3;
            size_t gi = ((size_t)(i*LL + r))*16 + h*4 + c4;
            *(uint4*)(KH + r*20 + c4*4) = kH4[gi];
        }
        const uint4* vH4 = (const uint4*)g_vTH;
        for (int idx = tid; idx < 1024; idx += 256){
            int d = idx >> 5, c4 = idx & 31;
            size_t gi = ((size_t)((i*NHEAD + h)*DHEAD + d))*32 + c4;
            *(uint4*)(VTH + d*132 + c4*4) = vH4[gi];
        }
    }

    // Q fragments: direct pre-split loads (this warp's 16 rows)
    const int j0 = half*128 + wid*16 + gid;
    uint32_t QHf[2][4], QLf[2][4];
    {
        const uint32_t* qH = g_qH + ((size_t)(i*LL + j0))*64 + h*16;
        const uint32_t* qL = g_qL + ((size_t)(i*LL + j0))*64 + h*16;
        #pragma unroll
        for (int ks = 0; ks < 2; ks++){
            QHf[ks][0] = qH[ks*8 + tig];
            QHf[ks][1] = qH[8*64 + ks*8 + tig];
            QHf[ks][2] = qH[ks*8 + tig + 4];
            QHf[ks][3] = qH[8*64 + ks*8 + tig + 4];
            QLf[ks][0] = qL[ks*8 + tig];
            QLf[ks][1] = qL[8*64 + ks*8 + tig];
            QLf[ks][2] = qL[ks*8 + tig + 4];
            QLf[ks][3] = qL[8*64 + ks*8 + tig + 4];
        }
    }
    __syncthreads();

    // ldmatrix per-lane bases (B side):
    const uint32_t kB0 = smaddr(KH)  + ((uint32_t)((gb>>1)*8 + li)*20  + (gb&1)*4) * 4;
    const uint32_t vB0 = smaddr(VTH) + ((uint32_t)((gb>>1)*8 + li)*132 + (gb&1)*4) * 4;

    float lrow[2], O[4][4];
    #pragma unroll
    for (int rr = 0; rr < 2; rr++) lrow[rr] = 0.f;
    #pragma unroll
    for (int nf = 0; nf < 4; nf++)
        #pragma unroll
        for (int q = 0; q < 4; q++) O[nf][q] = 0.f;

    for (int ch = 0; ch < 4; ch++){
        float S[8][4];
        #pragma unroll
        for (int nf = 0; nf < 8; nf++)
            #pragma unroll
            for (int q = 0; q < 4; q++) S[nf][q] = 0.f;

        // S = Q K^T (2-term fp16: Qh*K + Ql*K); log2 units
        #pragma unroll
        for (int ks = 0; ks < 2; ks++){
            #pragma unroll
            for (int np = 0; np < 4; np++){
                uint32_t B[4];
                ldsm4(B, kB0 + (uint32_t)((ch*64 + np*16)*20 + ks*8) * 4);
                #pragma unroll
                for (int c = 0; c < 2; c++){
                    int nf = 2*np + c;
                    mma16816(S[nf], QHf[ks], B[2*c], B[2*c+1]);
                    mma16816(S[nf], QLf[ks], B[2*c], B[2*c+1]);
                }
            }
        }

        // mask (fast path when all bits set) + single-pass exp2
        #pragma unroll
        for (int rr = 0; rr < 2; rr++){
            int j = j0 + rr*8;
            unsigned w0 = g_mask[j*8 + ch*2];
            unsigned w1 = g_mask[j*8 + ch*2 + 1];
            if ((w0 & w1) != 0xFFFFFFFFu){
                #pragma unroll
                for (int nf = 0; nf < 8; nf++){
                    #pragma unroll
                    for (int cc = 0; cc < 2; cc++){
                        int kb = nf*8 + 2*tig + cc;
                        unsigned w = (kb < 32) ? w0 : w1;
                        if (!((w >> (kb & 31)) & 1u)) S[nf][rr*2+cc] = -1e9f;
                    }
                }
            }
            float ls = 0.f;
            #pragma unroll
            for (int nf = 0; nf < 8; nf++){
                float p0 = exp2f(S[nf][rr*2]);
                float p1 = exp2f(S[nf][rr*2+1]);
                S[nf][rr*2] = p0; S[nf][rr*2+1] = p1;
                ls += p0 + p1;
            }
            lrow[rr] += ls;
        }

        // O += P V  (P split fp16 in registers; V single, ldmatrix)
        #pragma unroll
        for (int g = 0; g < 4; g++){
            uint32_t AH[4], AL[4];
            split2h(S[2*g][0],   S[2*g][1],   AH[0], AL[0]);
            split2h(S[2*g][2],   S[2*g][3],   AH[1], AL[1]);
            split2h(S[2*g+1][0], S[2*g+1][1], AH[2], AL[2]);
            split2h(S[2*g+1][2], S[2*g+1][3], AH[3], AL[3]);
            #pragma unroll
            for (int np = 0; np < 2; np++){
                uint32_t B[4];
                ldsm4(B, vB0 + (uint32_t)(np*16*132 + ch*32 + g*8) * 4);
                #pragma unroll
                for (int c = 0; c < 2; c++){
                    int nf = 2*np + c;
                    mma16816(O[nf], AH, B[2*c], B[2*c+1]);
                    mma16816(O[nf], AL, B[2*c], B[2*c+1]);
                }
            }
        }
    }

    // finalize + write (fp16 split for outproj A-operand)
    #pragma unroll
    for (int rr = 0; rr < 2; rr++){
        float l = lrow[rr];
        l += __shfl_xor_sync(0xffffffffu, l, 1);
        l += __shfl_xor_sync(0xffffffffu, l, 2);
        float inv = 1.f / l;
        int j = j0 + rr*8;
        size_t rb = (size_t)(i*LL + j)*64 + h*16;   // head h = pairs h*16..h*16+15
        #pragma unroll
        for (int nf = 0; nf < 4; nf++){
            float o0 = O[nf][rr*2]   * inv;
            float o1 = O[nf][rr*2+1] * inv;
            uint32_t hi, lo; split2h(o0, o1, hi, lo);
            g_attH[rb + nf*4 + tig] = hi;
            g_attL[rb + nf*4 + tig] = lo;
        }
    }
}

// ---------------- kernel 3: out projection + gate ----------------
// smem: att hi/lo [64][68] = 34.8KB; Wo via fragment LDG.
__global__ __launch_bounds__(256,3) void k_outproj(const float* __restrict__ bo,
                                                   float* __restrict__ out)
{
    extern __shared__ uint32_t sm[];
    uint32_t* AHs = sm;                 // 64*68
    uint32_t* ALs = sm + 64*WST;

    const int row0 = blockIdx.x * 64;
    const int tid = threadIdx.x;
    const int lane = tid & 31, wid = tid >> 5;
    const int gid = lane >> 2, tig = lane & 3;
    const int li = lane & 7, gb = lane >> 3;

    // stage activations (pure copy of pre-split fp16 data)
    {
        const uint4* aH4 = (const uint4*)g_attH;
        const uint4* aL4 = (const uint4*)g_attL;
        for (int idx = tid; idx < 1024; idx += 256){
            int r = idx >> 4, c4 = idx & 15;
            size_t gi = ((size_t)(row0 + r))*16 + c4;
            *(uint4*)(AHs + r*WST + c4*4) = aH4[gi];
            *(uint4*)(ALs + r*WST + c4*4) = aL4[gi];
        }
    }
    __syncthreads();

    const int wm = wid >> 2, wn = wid & 3;
    const int m0 = wm*32, n0 = wn*32;

    const uint32_t aOff = ((uint32_t)(m0 + (gb&1)*8 + li)*WST + (gb>>1)*4) * 4;
    const uint32_t aH0 = smaddr(AHs) + aOff;
    const uint32_t aL0 = smaddr(ALs) + aOff;
    const uint2* Wf = g_Wf[4] + (size_t)(wn*4)*8*32 + lane;

    float C[2][4][4];
    #pragma unroll
    for (int mi=0; mi<2; mi++)
        #pragma unroll
        for (int nf=0; nf<4; nf++)
            #pragma unroll
            for (int q=0; q<4; q++) C[mi][nf][q] = 0.f;

    #pragma unroll
    for (int ks = 0; ks < 8; ks++){
        uint32_t AH[2][4], AL[2][4];
        #pragma unroll
        for (int mi = 0; mi < 2; mi++){
            uint32_t o = (uint32_t)(mi*16*WST + ks*8) * 4;
            ldsm4(AH[mi], aH0 + o);
            ldsm4(AL[mi], aL0 + o);
        }
        #pragma unroll
        for (int nf = 0; nf < 4; nf++){
            uint2 B = Wf[(nf*8 + ks)*32];
            #pragma unroll
            for (int mi = 0; mi < 2; mi++){
                mma16816(C[mi][nf], AH[mi], B.x, B.y);
                mma16816(C[mi][nf], AL[mi], B.x, B.y);
            }
        }
    }

    #pragma unroll
    for (int mi = 0; mi < 2; mi++){
        #pragma unroll
        for (int nf = 0; nf < 4; nf++){
            int col = n0 + nf*8 + 2*tig;
            float b0 = bo[col], b1 = bo[col+1];
            int r0 = row0 + m0 + mi*16 + gid;
            size_t a0 = (size_t)r0*DD + col;
            size_t a1 = (size_t)(r0+8)*DD + col;
            float2 gt0 = *(const float2*)(g_gate + a0);
            float2 gt1 = *(const float2*)(g_gate + a1);
            *(float2*)(out + a0) = make_float2((C[mi][nf][0]+b0)*gt0.x, (C[mi][nf][1]+b1)*gt0.y);
            *(float2*)(out + a1) = make_float2((C[mi][nf][2]+b0)*gt1.x, (C[mi][nf][3]+b1)*gt1.y);
        }
    }
}

// ---------------- launch ----------------
extern "C" void kernel_launch(void* const* d_in, const int* in_sizes, int n_in,
                              void* d_out, int out_size)
{
    const float* pair = (const float*)d_in[0];
    const int*   mask = (const int*)d_in[1];
    const float* ln_g = (const float*)d_in[2];
    const float* ln_b = (const float*)d_in[3];
    const float* Wq = (const float*)d_in[4];  const float* bq = (const float*)d_in[5];
    const float* Wk = (const float*)d_in[6];  const float* bk = (const float*)d_in[7];
    const float* Wv = (const float*)d_in[8];  const float* bv = (const float*)d_in[9];
    const float* Wo = (const float*)d_in[10]; const float* bo = (const float*)d_in[11];
    const float* Wg = (const float*)d_in[12]; const float* bg = (const float*)d_in[13];
    float* out = (float*)d_out;

    const int smemP = (2*64*WST) * 4;               // 34816
    const int smemA = ATOT * 4;                      // 37376
    cudaFuncSetAttribute(k_lnproj,  cudaFuncAttributeMaxDynamicSharedMemorySize, smemP);
    cudaFuncSetAttribute(k_outproj, cudaFuncAttributeMaxDynamicSharedMemorySize, smemP);
    cudaFuncSetAttribute(k_attn,    cudaFuncAttributeMaxDynamicSharedMemorySize, smemA);

    k_prep<<<5, 256>>>(Wq, Wk, Wv, Wg, Wo);
    k_maskpack<<<1, 256>>>(mask);
    k_lnproj<<<NROWS/64, 256, smemP>>>(pair, ln_g, ln_b, bq, bk, bv, bg);
    dim3 ga(LL, NHEAD, 2);
    k_attn<<<ga, 256, smemA>>>();
    k_outproj<<<NROWS/64, 256, smemP>>>(bo, out);
}

// round 14
// speedup vs baseline: 1.1611x; 1.1611x over previous
#include <cuda_runtime.h>
#include <cuda_fp16.h>
#include <cstdint>
#include <math.h>

#define LL 256
#define DD 128
#define NHEAD 4
#define DHEAD 32
#define NROWS (LL*LL)   // 65536
#define WST 68          // packed-pair row stride (uint32) for PN/att smem images

// ---------------- scratch ----------------
// fragment-major weights: g_Wf[p][(nf*8+ks)*32+lane] = uint2{b0,b1} mma B-operands
__device__ uint2    g_Wf[5][4096];
__device__ uint32_t g_qH[(size_t)NROWS*64];   // q pre-scaled by log2e/sqrt(32), fp16 split hi
__device__ uint32_t g_qL[(size_t)NROWS*64];   // fp16 split lo
__device__ uint32_t g_kH[(size_t)NROWS*64];   // k single fp16 pairs
__device__ uint32_t g_vTH[(size_t)LL*NHEAD*DHEAD*128];  // v^T single fp16 pairs [i][h][d][j-pair]
__device__ float    g_gate[(size_t)NROWS*DD];
__device__ uint32_t g_attH[(size_t)NROWS*64]; // att fp16 split hi
__device__ uint32_t g_attL[(size_t)NROWS*64]; // fp16 split lo
__device__ unsigned g_mask[LL*8];

// ---------------- helpers ----------------
__device__ __forceinline__ uint32_t packh(__half a, __half b){
    __half2 t; t.x = a; t.y = b;
    return *reinterpret_cast<uint32_t*>(&t);
}
__device__ __forceinline__ uint32_t pack1h(float x0, float x1){
    return packh(__float2half_rn(x0), __float2half_rn(x1));
}
__device__ __forceinline__ void split2h(float x0, float x1, uint32_t& hi, uint32_t& lo){
    __half h0 = __float2half_rn(x0);
    __half h1 = __float2half_rn(x1);
    __half l0 = __float2half_rn(x0 - __half2float(h0));
    __half l1 = __float2half_rn(x1 - __half2float(h1));
    hi = packh(h0, h1); lo = packh(l0, l1);
}
__device__ __forceinline__ void split1h(float x, __half& h, __half& l){
    h = __float2half_rn(x);
    l = __float2half_rn(x - __half2float(h));
}
__device__ __forceinline__ void mma16816(float* c, const uint32_t* a, uint32_t b0, uint32_t b1){
    asm volatile("mma.sync.aligned.m16n8k16.row.col.f32.f16.f16.f32 "
        "{%0,%1,%2,%3}, {%4,%5,%6,%7}, {%8,%9}, {%0,%1,%2,%3};\n"
        : "+f"(c[0]), "+f"(c[1]), "+f"(c[2]), "+f"(c[3])
        : "r"(a[0]), "r"(a[1]), "r"(a[2]), "r"(a[3]), "r"(b0), "r"(b1));
}
__device__ __forceinline__ uint32_t smaddr(const void* p){
    return (uint32_t)__cvta_generic_to_shared(p);
}
__device__ __forceinline__ void ldsm4(uint32_t* r, uint32_t a){
    asm volatile("ldmatrix.sync.aligned.m8n8.x4.shared.b16 {%0,%1,%2,%3}, [%4];"
        : "=r"(r[0]), "=r"(r[1]), "=r"(r[2]), "=r"(r[3]) : "r"(a));
}

// ---------------- kernel: prep weights into fragment-major table ----------------
__global__ void k_prep(const float* __restrict__ Wq, const float* __restrict__ Wk,
                       const float* __restrict__ Wv, const float* __restrict__ Wg,
                       const float* __restrict__ Wo)
{
    int m = blockIdx.x;
    const float* W = (m==0)?Wq:(m==1)?Wk:(m==2)?Wv:(m==3)?Wg:Wo;
    for (int idx = threadIdx.x; idx < 4096; idx += blockDim.x){
        int lane = idx & 31;
        int ks = (idx >> 5) & 7;
        int nf = idx >> 8;
        int e = nf*8 + (lane >> 2);
        int tig = lane & 3;
        int pd0 = ks*8 + tig, pd1 = pd0 + 4;
        uint2 v;
        v.x = pack1h(W[e*DD + 2*pd0], W[e*DD + 2*pd0 + 1]);
        v.y = pack1h(W[e*DD + 2*pd1], W[e*DD + 2*pd1 + 1]);
        g_Wf[m][idx] = v;
    }
}

// ---------------- kernel: pack mask ----------------
__global__ void k_maskpack(const int* __restrict__ mask)
{
    int j = threadIdx.x;
    const int* mrow = mask + (size_t)j*LL;
    #pragma unroll
    for (int w = 0; w < 8; w++){
        unsigned bits = 0;
        #pragma unroll
        for (int b = 0; b < 32; b++) bits |= (mrow[w*32+b] != 0 ? 1u : 0u) << b;
        g_mask[j*8 + w] = bits;
    }
}

// ---------------- kernel 1: LayerNorm + q/k/v/gate projections ----------------
// 256 threads, 64 rows/block. smem: PN hi/lo [64][68] = 34.8KB. Weights via LDG.
__global__ __launch_bounds__(256,2) void k_lnproj(
    const float* __restrict__ pair,
    const float* __restrict__ ln_g, const float* __restrict__ ln_b,
    const float* __restrict__ bq, const float* __restrict__ bk,
    const float* __restrict__ bv, const float* __restrict__ bg)
{
    extern __shared__ uint32_t sm[];
    uint32_t* PNH = sm;                 // 64*68
    uint32_t* PNL = sm + 64*WST;
    __half* PNHh = (__half*)PNH;
    __half* PNLh = (__half*)PNL;

    const int row0 = blockIdx.x * 64;
    const int tid = threadIdx.x;
    const int lane = tid & 31, wid = tid >> 5;
    const int gid = lane >> 2, tig = lane & 3;
    const int li = lane & 7, gb = lane >> 3;
    const float QSC = 0.17677669529663687f * 1.4426950408889634f;  // (1/sqrt 32)*log2(e)

    // ---- LayerNorm: 8 warps x 8 rows, fp16 split into smem ----
    {
        float lg[4], lb[4];
        #pragma unroll
        for (int t = 0; t < 4; t++){ lg[t] = ln_g[lane + 32*t]; lb[t] = ln_b[lane + 32*t]; }
        for (int rr = 0; rr < 8; rr++){
            int r = wid*8 + rr;
            const float* x = pair + (size_t)(row0 + r)*DD;
            float v[4];
            #pragma unroll
            for (int t = 0; t < 4; t++) v[t] = x[lane + 32*t];
            float s = v[0]+v[1]+v[2]+v[3];
            #pragma unroll
            for (int o = 16; o > 0; o >>= 1) s += __shfl_xor_sync(0xffffffffu, s, o);
            float mu = s * (1.f/128.f);
            float sq = 0.f;
            #pragma unroll
            for (int t = 0; t < 4; t++){ v[t] -= mu; sq += v[t]*v[t]; }
            #pragma unroll
            for (int o = 16; o > 0; o >>= 1) sq += __shfl_xor_sync(0xffffffffu, sq, o);
            float rstd = rsqrtf(sq*(1.f/128.f) + 1e-5f);
            #pragma unroll
            for (int t = 0; t < 4; t++){
                float pn = v[t]*rstd*lg[t] + lb[t];
                __half h, l; split1h(pn, h, l);
                PNHh[r*(2*WST) + lane + 32*t] = h;
                PNLh[r*(2*WST) + lane + 32*t] = l;
            }
        }
    }
    __syncthreads();

    const int wm = wid >> 2, wn = wid & 3;
    const int m0 = wm*32, n0 = wn*32;

    // ldmatrix per-lane bases (A side)
    const uint32_t aOff = ((uint32_t)(m0 + (gb&1)*8 + li)*WST + (gb>>1)*4) * 4;
    const uint32_t aH0 = smaddr(PNH) + aOff;
    const uint32_t aL0 = smaddr(PNL) + aOff;

    // projection order: q(0), k(1), gate(3), v(2) — PN must stay live until v (last)
    #pragma unroll
    for (int pi = 0; pi < 4; pi++){
        const int p = (pi==2) ? 3 : (pi==3) ? 2 : pi;
        const bool full = (p != 3);   // gate projection: 1-term
        const uint2* Wf = g_Wf[p] + (size_t)(wn*4)*8*32 + lane;

        float C[2][4][4];
        #pragma unroll
        for (int mi=0; mi<2; mi++)
            #pragma unroll
            for (int nf=0; nf<4; nf++)
                #pragma unroll
                for (int q=0; q<4; q++) C[mi][nf][q] = 0.f;

        #pragma unroll
        for (int ks = 0; ks < 8; ks++){
            uint32_t AH[2][4], AL[2][4];
            #pragma unroll
            for (int mi = 0; mi < 2; mi++){
                uint32_t o = (uint32_t)(mi*16*WST + ks*8) * 4;
                ldsm4(AH[mi], aH0 + o);
                if (full) ldsm4(AL[mi], aL0 + o);
            }
            #pragma unroll
            for (int nf = 0; nf < 4; nf++){
                uint2 B = Wf[(nf*8 + ks)*32];
                #pragma unroll
                for (int mi = 0; mi < 2; mi++){
                    mma16816(C[mi][nf], AH[mi], B.x, B.y);
                    if (full) mma16816(C[mi][nf], AL[mi], B.x, B.y);
                }
            }
        }

        if (p == 2) __syncthreads();   // v is last: all warps done reading PN before vt overlay

        const float* bias = (p==0)?bq:(p==1)?bk:(p==2)?bv:bg;
        #pragma unroll
        for (int mi = 0; mi < 2; mi++){
            #pragma unroll
            for (int nf = 0; nf < 4; nf++){
                int col = n0 + nf*8 + 2*tig;
                float b0 = bias[col], b1 = bias[col+1];
                float v00 = C[mi][nf][0] + b0, v01 = C[mi][nf][1] + b1;
                float v10 = C[mi][nf][2] + b0, v11 = C[mi][nf][3] + b1;
                int rl = m0 + mi*16 + gid;        // local row 0..63
                int r0 = row0 + rl;
                if (p == 0){
                    v00 *= QSC; v01 *= QSC; v10 *= QSC; v11 *= QSC;
                    uint32_t hi, lo;
                    split2h(v00, v01, hi, lo);
                    g_qH[(size_t)r0*64 + (col>>1)] = hi; g_qL[(size_t)r0*64 + (col>>1)] = lo;
                    split2h(v10, v11, hi, lo);
                    g_qH[(size_t)(r0+8)*64 + (col>>1)] = hi; g_qL[(size_t)(r0+8)*64 + (col>>1)] = lo;
                } else if (p == 1){
                    g_kH[(size_t)r0*64 + (col>>1)]     = pack1h(v00, v01);
                    g_kH[(size_t)(r0+8)*64 + (col>>1)] = pack1h(v10, v11);
                } else if (p == 2){
                    float* vt = (float*)sm;       // [64][131] overlay on PN region
                    vt[rl*131 + col] = v00; vt[rl*131 + col + 1] = v01;
                    vt[(rl+8)*131 + col] = v10; vt[(rl+8)*131 + col + 1] = v11;
                } else {
                    v00 = 1.f/(1.f+__expf(-v00)); v01 = 1.f/(1.f+__expf(-v01));
                    v10 = 1.f/(1.f+__expf(-v10)); v11 = 1.f/(1.f+__expf(-v11));
                    *(float2*)(g_gate + (size_t)r0*DD + col)     = make_float2(v00, v01);
                    *(float2*)(g_gate + (size_t)(r0+8)*DD + col) = make_float2(v10, v11);
                }
            }
        }
    }

    __syncthreads();
    // transpose v tile -> g_vTH (single fp16) (block covers j0..j0+63 of row i)
    {
        const int i_ = row0 >> 8, j0_ = row0 & 255;
        const float* vt = (const float*)sm;
        for (int idx = tid; idx < 4096; idx += 256){
            int h_ = idx >> 10;
            int rem = idx & 1023;
            int d_ = rem >> 5;
            int jp = rem & 31;
            float v0 = vt[(jp*2)*131 + h_*32 + d_];
            float v1 = vt[(jp*2+1)*131 + h_*32 + d_];
            size_t o = ((size_t)((i_*NHEAD + h_)*DHEAD + d_))*128 + (j0_>>1) + jp;
            g_vTH[o] = pack1h(v0, v1);
        }
    }
}

// ---------------- kernel 2: attention per (i,h,half) ----------------
// 256 threads / 8 warps, each warp owns 16 query rows. 2 blocks per (i,h).
// fp16 2-term: Q split (A), K single (B); P split (A), V single (B). ldmatrix B loads.
// smem (uint32): KH[256][20], VTH[32][132] = 37.4KB
#define AKH 0
#define AVH 5120
#define ATOT 9344
__global__ __launch_bounds__(256,2) void k_attn()
{
    extern __shared__ uint32_t sm[];
    uint32_t* KH = sm + AKH;    // [256][20]
    uint32_t* VTH = sm + AVH;   // [32][132]

    const int i = blockIdx.x, h = blockIdx.y, half = blockIdx.z;
    const int tid = threadIdx.x;
    const int lane = tid & 31, wid = tid >> 5;
    const int gid = lane >> 2, tig = lane & 3;
    const int li = lane & 7, gb = lane >> 3;

    // stage K and V^T (pure copies of fp16-packed data)
    {
        const uint4* kH4 = (const uint4*)g_kH;
        for (int idx = tid; idx < 1024; idx += 256){
            int r = idx >> 2, c4 = idx & 3;
            size_t gi = ((size_t)(i*LL + r))*16 + h*4 + c4;
            *(uint4*)(KH + r*20 + c4*4) = kH4[gi];
        }
        const uint4* vH4 = (const uint4*)g_vTH;
        for (int idx = tid; idx < 1024; idx += 256){
            int d = idx >> 5, c4 = idx & 31;
            size_t gi = ((size_t)((i*NHEAD + h)*DHEAD + d))*32 + c4;
            *(uint4*)(VTH + d*132 + c4*4) = vH4[gi];
        }
    }

    // Q fragments: direct pre-split loads (this warp's 16 rows)
    const int j0 = half*128 + wid*16 + gid;
    uint32_t QHf[2][4], QLf[2][4];
    {
        const uint32_t* qH = g_qH + ((size_t)(i*LL + j0))*64 + h*16;
        const uint32_t* qL = g_qL + ((size_t)(i*LL + j0))*64 + h*16;
        #pragma unroll
        for (int ks = 0; ks < 2; ks++){
            QHf[ks][0] = qH[ks*8 + tig];
            QHf[ks][1] = qH[8*64 + ks*8 + tig];
            QHf[ks][2] = qH[ks*8 + tig + 4];
            QHf[ks][3] = qH[8*64 + ks*8 + tig + 4];
            QLf[ks][0] = qL[ks*8 + tig];
            QLf[ks][1] = qL[8*64 + ks*8 + tig];
            QLf[ks][2] = qL[ks*8 + tig + 4];
            QLf[ks][3] = qL[8*64 + ks*8 + tig + 4];
        }
    }
    __syncthreads();

    // ldmatrix per-lane bases (B side):
    const uint32_t kB0 = smaddr(KH)  + ((uint32_t)((gb>>1)*8 + li)*20  + (gb&1)*4) * 4;
    const uint32_t vB0 = smaddr(VTH) + ((uint32_t)((gb>>1)*8 + li)*132 + (gb&1)*4) * 4;

    float lrow[2], O[4][4];
    #pragma unroll
    for (int rr = 0; rr < 2; rr++) lrow[rr] = 0.f;
    #pragma unroll
    for (int nf = 0; nf < 4; nf++)
        #pragma unroll
        for (int q = 0; q < 4; q++) O[nf][q] = 0.f;

    for (int ch = 0; ch < 4; ch++){
        float S[8][4];
        #pragma unroll
        for (int nf = 0; nf < 8; nf++)
            #pragma unroll
            for (int q = 0; q < 4; q++) S[nf][q] = 0.f;

        // S = Q K^T (2-term fp16: Qh*K + Ql*K); log2 units
        #pragma unroll
        for (int ks = 0; ks < 2; ks++){
            #pragma unroll
            for (int np = 0; np < 4; np++){
                uint32_t B[4];
                ldsm4(B, kB0 + (uint32_t)((ch*64 + np*16)*20 + ks*8) * 4);
                #pragma unroll
                for (int c = 0; c < 2; c++){
                    int nf = 2*np + c;
                    mma16816(S[nf], QHf[ks], B[2*c], B[2*c+1]);
                    mma16816(S[nf], QLf[ks], B[2*c], B[2*c+1]);
                }
            }
        }

        // mask (fast path when all bits set) + single-pass exp2
        #pragma unroll
        for (int rr = 0; rr < 2; rr++){
            int j = j0 + rr*8;
            unsigned w0 = g_mask[j*8 + ch*2];
            unsigned w1 = g_mask[j*8 + ch*2 + 1];
            if ((w0 & w1) != 0xFFFFFFFFu){
                #pragma unroll
                for (int nf = 0; nf < 8; nf++){
                    #pragma unroll
                    for (int cc = 0; cc < 2; cc++){
                        int kb = nf*8 + 2*tig + cc;
                        unsigned w = (kb < 32) ? w0 : w1;
                        if (!((w >> (kb & 31)) & 1u)) S[nf][rr*2+cc] = -1e9f;
                    }
                }
            }
            float ls = 0.f;
            #pragma unroll
            for (int nf = 0; nf < 8; nf++){
                float p0 = exp2f(S[nf][rr*2]);
                float p1 = exp2f(S[nf][rr*2+1]);
                S[nf][rr*2] = p0; S[nf][rr*2+1] = p1;
                ls += p0 + p1;
            }
            lrow[rr] += ls;
        }

        // O += P V  (P split fp16 in registers; V single, ldmatrix)
        #pragma unroll
        for (int g = 0; g < 4; g++){
            uint32_t AH[4], AL[4];
            split2h(S[2*g][0],   S[2*g][1],   AH[0], AL[0]);
            split2h(S[2*g][2],   S[2*g][3],   AH[1], AL[1]);
            split2h(S[2*g+1][0], S[2*g+1][1], AH[2], AL[2]);
            split2h(S[2*g+1][2], S[2*g+1][3], AH[3], AL[3]);
            #pragma unroll
            for (int np = 0; np < 2; np++){
                uint32_t B[4];
                ldsm4(B, vB0 + (uint32_t)(np*16*132 + ch*32 + g*8) * 4);
                #pragma unroll
                for (int c = 0; c < 2; c++){
                    int nf = 2*np + c;
                    mma16816(O[nf], AH, B[2*c], B[2*c+1]);
                    mma16816(O[nf], AL, B[2*c], B[2*c+1]);
                }
            }
        }
    }

    // finalize + write (fp16 split for outproj A-operand)
    #pragma unroll
    for (int rr = 0; rr < 2; rr++){
        float l = lrow[rr];
        l += __shfl_xor_sync(0xffffffffu, l, 1);
        l += __shfl_xor_sync(0xffffffffu, l, 2);
        float inv = 1.f / l;
        int j = j0 + rr*8;
        size_t rb = (size_t)(i*LL + j)*64 + h*16;   // head h = pairs h*16..h*16+15
        #pragma unroll
        for (int nf = 0; nf < 4; nf++){
            float o0 = O[nf][rr*2]   * inv;
            float o1 = O[nf][rr*2+1] * inv;
            uint32_t hi, lo; split2h(o0, o1, hi, lo);
            g_attH[rb + nf*4 + tig] = hi;
            g_attL[rb + nf*4 + tig] = lo;
        }
    }
}

// ---------------- kernel 3: out projection + gate ----------------
// smem: att hi/lo [64][68] = 34.8KB; Wo via fragment LDG.
__global__ __launch_bounds__(256,2) void k_outproj(const float* __restrict__ bo,
                                                   float* __restrict__ out)
{
    extern __shared__ uint32_t sm[];
    uint32_t* AHs = sm;                 // 64*68
    uint32_t* ALs = sm + 64*WST;

    const int row0 = blockIdx.x * 64;
    const int tid = threadIdx.x;
    const int lane = tid & 31, wid = tid >> 5;
    const int gid = lane >> 2, tig = lane & 3;
    const int li = lane & 7, gb = lane >> 3;

    // stage activations (pure copy of pre-split fp16 data)
    {
        const uint4* aH4 = (const uint4*)g_attH;
        const uint4* aL4 = (const uint4*)g_attL;
        for (int idx = tid; idx < 1024; idx += 256){
            int r = idx >> 4, c4 = idx & 15;
            size_t gi = ((size_t)(row0 + r))*16 + c4;
            *(uint4*)(AHs + r*WST + c4*4) = aH4[gi];
            *(uint4*)(ALs + r*WST + c4*4) = aL4[gi];
        }
    }
    __syncthreads();

    const int wm = wid >> 2, wn = wid & 3;
    const int m0 = wm*32, n0 = wn*32;

    const uint32_t aOff = ((uint32_t)(m0 + (gb&1)*8 + li)*WST + (gb>>1)*4) * 4;
    const uint32_t aH0 = smaddr(AHs) + aOff;
    const uint32_t aL0 = smaddr(ALs) + aOff;
    const uint2* Wf = g_Wf[4] + (size_t)(wn*4)*8*32 + lane;

    float C[2][4][4];
    #pragma unroll
    for (int mi=0; mi<2; mi++)
        #pragma unroll
        for (int nf=0; nf<4; nf++)
            #pragma unroll
            for (int q=0; q<4; q++) C[mi][nf][q] = 0.f;

    #pragma unroll
    for (int ks = 0; ks < 8; ks++){
        uint32_t AH[2][4], AL[2][4];
        #pragma unroll
        for (int mi = 0; mi < 2; mi++){
            uint32_t o = (uint32_t)(mi*16*WST + ks*8) * 4;
            ldsm4(AH[mi], aH0 + o);
            ldsm4(AL[mi], aL0 + o);
        }
        #pragma unroll
        for (int nf = 0; nf < 4; nf++){
            uint2 B = Wf[(nf*8 + ks)*32];
            #pragma unroll
            for (int mi = 0; mi < 2; mi++){
                mma16816(C[mi][nf], AH[mi], B.x, B.y);
                mma16816(C[mi][nf], AL[mi], B.x, B.y);
            }
        }
    }

    #pragma unroll
    for (int mi = 0; mi < 2; mi++){
        #pragma unroll
        for (int nf = 0; nf < 4; nf++){
            int col = n0 + nf*8 + 2*tig;
            float b0 = bo[col], b1 = bo[col+1];
            int r0 = row0 + m0 + mi*16 + gid;
            size_t a0 = (size_t)r0*DD + col;
            size_t a1 = (size_t)(r0+8)*DD + col;
            float2 gt0 = *(const float2*)(g_gate + a0);
            float2 gt1 = *(const float2*)(g_gate + a1);
            *(float2*)(out + a0) = make_float2((C[mi][nf][0]+b0)*gt0.x, (C[mi][nf][1]+b1)*gt0.y);
            *(float2*)(out + a1) = make_float2((C[mi][nf][2]+b0)*gt1.x, (C[mi][nf][3]+b1)*gt1.y);
        }
    }
}

// ---------------- launch ----------------
extern "C" void kernel_launch(void* const* d_in, const int* in_sizes, int n_in,
                              void* d_out, int out_size)
{
    const float* pair = (const float*)d_in[0];
    const int*   mask = (const int*)d_in[1];
    const float* ln_g = (const float*)d_in[2];
    const float* ln_b = (const float*)d_in[3];
    const float* Wq = (const float*)d_in[4];  const float* bq = (const float*)d_in[5];
    const float* Wk = (const float*)d_in[6];  const float* bk = (const float*)d_in[7];
    const float* Wv = (const float*)d_in[8];  const float* bv = (const float*)d_in[9];
    const float* Wo = (const float*)d_in[10]; const float* bo = (const float*)d_in[11];
    const float* Wg = (const float*)d_in[12]; const float* bg = (const float*)d_in[13];
    float* out = (float*)d_out;

    const int smemP = (2*64*WST) * 4;               // 34816
    const int smemA = ATOT * 4;                      // 37376
    cudaFuncSetAttribute(k_lnproj,  cudaFuncAttributeMaxDynamicSharedMemorySize, smemP);
    cudaFuncSetAttribute(k_outproj, cudaFuncAttributeMaxDynamicSharedMemorySize, smemP);
    cudaFuncSetAttribute(k_attn,    cudaFuncAttributeMaxDynamicSharedMemorySize, smemA);

    k_prep<<<5, 256>>>(Wq, Wk, Wv, Wg, Wo);
    k_maskpack<<<1, 256>>>(mask);
    k_lnproj<<<NROWS/64, 256, smemP>>>(pair, ln_g, ln_b, bq, bk, bv, bg);
    dim3 ga(LL, NHEAD, 2);
    k_attn<<<ga, 256, smemA>>>();
    k_outproj<<<NROWS/64, 256, smemP>>>(bo, out);
}

// round 15
// speedup vs baseline: 1.2263x; 1.0561x over previous
#include <cuda_runtime.h>
#include <cuda_fp16.h>
#include <cstdint>
#include <math.h>

#define LL 256
#define DD 128
#define NHEAD 4
#define DHEAD 32
#define NROWS (LL*LL)   // 65536
#define WST 68          // packed-pair row stride (uint32) for smem images

// ---------------- scratch ----------------
__device__ uint32_t g_WH[5*128*WST];          // weights fp16 packed pairs (smem image layout)
__device__ uint32_t g_qH[(size_t)NROWS*64];   // q pre-scaled by log2e/sqrt(32), fp16 split hi
__device__ uint32_t g_qL[(size_t)NROWS*64];   // fp16 split lo
__device__ uint32_t g_kH[(size_t)NROWS*64];   // k single fp16 pairs
__device__ uint32_t g_vTH[(size_t)LL*NHEAD*DHEAD*128];  // v^T single fp16 pairs [i][h][d][j-pair]
__device__ uint32_t g_gateP[(size_t)NROWS*64];// gate as packed fp16 pairs
__device__ uint32_t g_attH[(size_t)NROWS*64]; // att fp16 split hi
__device__ uint32_t g_attL[(size_t)NROWS*64]; // fp16 split lo
__device__ unsigned g_mask[LL*8];

// ---------------- helpers ----------------
__device__ __forceinline__ uint32_t packh(__half a, __half b){
    __half2 t; t.x = a; t.y = b;
    return *reinterpret_cast<uint32_t*>(&t);
}
__device__ __forceinline__ uint32_t pack1h(float x0, float x1){
    return packh(__float2half_rn(x0), __float2half_rn(x1));
}
__device__ __forceinline__ void split2h(float x0, float x1, uint32_t& hi, uint32_t& lo){
    __half h0 = __float2half_rn(x0);
    __half h1 = __float2half_rn(x1);
    __half l0 = __float2half_rn(x0 - __half2float(h0));
    __half l1 = __float2half_rn(x1 - __half2float(h1));
    hi = packh(h0, h1); lo = packh(l0, l1);
}
__device__ __forceinline__ void split1h(float x, __half& h, __half& l){
    h = __float2half_rn(x);
    l = __float2half_rn(x - __half2float(h));
}
__device__ __forceinline__ void mma16816(float* c, const uint32_t* a, uint32_t b0, uint32_t b1){
    asm volatile("mma.sync.aligned.m16n8k16.row.col.f32.f16.f16.f32 "
        "{%0,%1,%2,%3}, {%4,%5,%6,%7}, {%8,%9}, {%0,%1,%2,%3};\n"
        : "+f"(c[0]), "+f"(c[1]), "+f"(c[2]), "+f"(c[3])
        : "r"(a[0]), "r"(a[1]), "r"(a[2]), "r"(a[3]), "r"(b0), "r"(b1));
}
__device__ __forceinline__ uint32_t smaddr(const void* p){
    return (uint32_t)__cvta_generic_to_shared(p);
}
__device__ __forceinline__ void ldsm4(uint32_t* r, uint32_t a){
    asm volatile("ldmatrix.sync.aligned.m8n8.x4.shared.b16 {%0,%1,%2,%3}, [%4];"
        : "=r"(r[0]), "=r"(r[1]), "=r"(r[2]), "=r"(r[3]) : "r"(a));
}

// ---------------- kernel: prep weights (fp16 pairs along d) ----------------
__global__ void k_prep(const float* __restrict__ Wq, const float* __restrict__ Wk,
                       const float* __restrict__ Wv, const float* __restrict__ Wg,
                       const float* __restrict__ Wo)
{
    int m = blockIdx.x;
    const float* W = (m==0)?Wq:(m==1)?Wk:(m==2)?Wv:(m==3)?Wg:Wo;
    uint32_t* H = g_WH + m*128*WST;
    for (int idx = threadIdx.x; idx < 128*WST; idx += blockDim.x){
        int e = idx / WST, p = idx % WST;
        uint32_t hv = 0;
        if (p < 64) hv = pack1h(W[e*DD + 2*p], W[e*DD + 2*p + 1]);
        H[idx] = hv;
    }
}

// ---------------- kernel: pack mask ----------------
__global__ void k_maskpack(const int* __restrict__ mask)
{
    int j = threadIdx.x;
    const int* mrow = mask + (size_t)j*LL;
    #pragma unroll
    for (int w = 0; w < 8; w++){
        unsigned bits = 0;
        #pragma unroll
        for (int b = 0; b < 32; b++) bits |= (mrow[w*32+b] != 0 ? 1u : 0u) << b;
        g_mask[j*8 + w] = bits;
    }
}

// ---------------- kernel 1: LayerNorm + q/k/v/gate projections ----------------
// 512 threads / 16 warps, 128 rows/block. smem: PN hi/lo [128][68] + W [128][68] = 104.4KB
__global__ __launch_bounds__(512,1) void k_lnproj(
    const float* __restrict__ pair,
    const float* __restrict__ ln_g, const float* __restrict__ ln_b,
    const float* __restrict__ bq, const float* __restrict__ bk,
    const float* __restrict__ bv, const float* __restrict__ bg)
{
    extern __shared__ uint32_t sm[];
    uint32_t* PNH = sm;                 // 128*68
    uint32_t* PNL = sm + 128*WST;
    uint32_t* WH  = sm + 2*128*WST;     // 128*68
    __half* PNHh = (__half*)PNH;
    __half* PNLh = (__half*)PNL;

    const int row0 = blockIdx.x * 128;
    const int tid = threadIdx.x;
    const int lane = tid & 31, wid = tid >> 5;     // wid 0..15
    const int gid = lane >> 2, tig = lane & 3;
    const int li = lane & 7, gb = lane >> 3;
    const float QSC = 0.17677669529663687f * 1.4426950408889634f;  // (1/sqrt 32)*log2(e)

    // ---- LayerNorm: 16 warps x 8 rows, fp16 split into smem ----
    {
        float lg[4], lb[4];
        #pragma unroll
        for (int t = 0; t < 4; t++){ lg[t] = ln_g[lane + 32*t]; lb[t] = ln_b[lane + 32*t]; }
        for (int rr = 0; rr < 8; rr++){
            int r = wid*8 + rr;
            const float* x = pair + (size_t)(row0 + r)*DD;
            float v[4];
            #pragma unroll
            for (int t = 0; t < 4; t++) v[t] = x[lane + 32*t];
            float s = v[0]+v[1]+v[2]+v[3];
            #pragma unroll
            for (int o = 16; o > 0; o >>= 1) s += __shfl_xor_sync(0xffffffffu, s, o);
            float mu = s * (1.f/128.f);
            float sq = 0.f;
            #pragma unroll
            for (int t = 0; t < 4; t++){ v[t] -= mu; sq += v[t]*v[t]; }
            #pragma unroll
            for (int o = 16; o > 0; o >>= 1) sq += __shfl_xor_sync(0xffffffffu, sq, o);
            float rstd = rsqrtf(sq*(1.f/128.f) + 1e-5f);
            #pragma unroll
            for (int t = 0; t < 4; t++){
                float pn = v[t]*rstd*lg[t] + lb[t];
                __half h, l; split1h(pn, h, l);
                PNHh[r*(2*WST) + lane + 32*t] = h;
                PNLh[r*(2*WST) + lane + 32*t] = l;
            }
        }
    }
    __syncthreads();

    const int wm = wid >> 2, wn = wid & 3;         // 4x4 warp grid
    const int m0 = wm*32, n0 = wn*32;

    // ldmatrix per-lane bases
    const uint32_t aOff = ((uint32_t)(m0 + (gb&1)*8 + li)*WST + (gb>>1)*4) * 4;
    const uint32_t aH0 = smaddr(PNH) + aOff;
    const uint32_t aL0 = smaddr(PNL) + aOff;
    const uint32_t bW0 = smaddr(WH) + ((uint32_t)(n0 + (gb>>1)*8 + li)*WST + (gb&1)*4) * 4;

    // projection order: q(0), k(1), gate(3), v(2) — PN must stay live until v (last)
    #pragma unroll
    for (int pi = 0; pi < 4; pi++){
        const int p = (pi==2) ? 3 : (pi==3) ? 2 : pi;
        const bool full = (p != 3);   // gate projection: 1-term

        // stage weights into smem
        {
            const float4* sH = (const float4*)(g_WH + p*128*WST);
            float4* dH = (float4*)WH;
            for (int idx = tid; idx < 128*WST/4; idx += 512) dH[idx] = sH[idx];
        }
        __syncthreads();

        float C[2][4][4];
        #pragma unroll
        for (int mi=0; mi<2; mi++)
            #pragma unroll
            for (int nf=0; nf<4; nf++)
                #pragma unroll
                for (int q=0; q<4; q++) C[mi][nf][q] = 0.f;

        #pragma unroll
        for (int ks = 0; ks < 8; ks++){
            uint32_t AH[2][4], AL[2][4], B[2][4];
            #pragma unroll
            for (int mi = 0; mi < 2; mi++){
                uint32_t o = (uint32_t)(mi*16*WST + ks*8) * 4;
                ldsm4(AH[mi], aH0 + o);
                if (full) ldsm4(AL[mi], aL0 + o);
            }
            #pragma unroll
            for (int np = 0; np < 2; np++)
                ldsm4(B[np], bW0 + (uint32_t)(np*16*WST + ks*8) * 4);
            #pragma unroll
            for (int np = 0; np < 2; np++){
                #pragma unroll
                for (int c = 0; c < 2; c++){
                    int nf = 2*np + c;
                    #pragma unroll
                    for (int mi = 0; mi < 2; mi++){
                        mma16816(C[mi][nf], AH[mi], B[np][2*c], B[np][2*c+1]);
                        if (full) mma16816(C[mi][nf], AL[mi], B[np][2*c], B[np][2*c+1]);
                    }
                }
            }
        }

        if (p == 2) __syncthreads();   // v is last: all warps done reading PN before vt overlay

        const float* bias = (p==0)?bq:(p==1)?bk:(p==2)?bv:bg;
        #pragma unroll
        for (int mi = 0; mi < 2; mi++){
            #pragma unroll
            for (int nf = 0; nf < 4; nf++){
                int col = n0 + nf*8 + 2*tig;
                float b0 = bias[col], b1 = bias[col+1];
                float v00 = C[mi][nf][0] + b0, v01 = C[mi][nf][1] + b1;
                float v10 = C[mi][nf][2] + b0, v11 = C[mi][nf][3] + b1;
                int rl = m0 + mi*16 + gid;        // local row 0..127
                int r0 = row0 + rl;
                if (p == 0){
                    v00 *= QSC; v01 *= QSC; v10 *= QSC; v11 *= QSC;
                    uint32_t hi, lo;
                    split2h(v00, v01, hi, lo);
                    g_qH[(size_t)r0*64 + (col>>1)] = hi; g_qL[(size_t)r0*64 + (col>>1)] = lo;
                    split2h(v10, v11, hi, lo);
                    g_qH[(size_t)(r0+8)*64 + (col>>1)] = hi; g_qL[(size_t)(r0+8)*64 + (col>>1)] = lo;
                } else if (p == 1){
                    g_kH[(size_t)r0*64 + (col>>1)]     = pack1h(v00, v01);
                    g_kH[(size_t)(r0+8)*64 + (col>>1)] = pack1h(v10, v11);
                } else if (p == 2){
                    float* vt = (float*)sm;       // [128][131] overlay on PN region
                    vt[rl*131 + col] = v00; vt[rl*131 + col + 1] = v01;
                    vt[(rl+8)*131 + col] = v10; vt[(rl+8)*131 + col + 1] = v11;
                } else {
                    v00 = 1.f/(1.f+__expf(-v00)); v01 = 1.f/(1.f+__expf(-v01));
                    v10 = 1.f/(1.f+__expf(-v10)); v11 = 1.f/(1.f+__expf(-v11));
                    g_gateP[(size_t)r0*64 + (col>>1)]     = pack1h(v00, v01);
                    g_gateP[(size_t)(r0+8)*64 + (col>>1)] = pack1h(v10, v11);
                }
            }
        }
        __syncthreads();   // WH (and PN at p==2) consumers done before next stage / transpose
    }

    // transpose v tile -> g_vTH (single fp16) (block covers j0..j0+127 of row i)
    {
        const int i_ = row0 >> 8, j0_ = row0 & 255;
        const float* vt = (const float*)sm;
        for (int idx = tid; idx < 8192; idx += 512){
            int h_ = idx >> 11;
            int rem = idx & 2047;
            int d_ = rem >> 6;
            int jp = rem & 63;
            float v0 = vt[(jp*2)*131   + h_*32 + d_];
            float v1 = vt[(jp*2+1)*131 + h_*32 + d_];
            size_t o = ((size_t)((i_*NHEAD + h_)*DHEAD + d_))*128 + (j0_>>1) + jp;
            g_vTH[o] = pack1h(v0, v1);
        }
    }
}

// ---------------- kernel 2: attention per (i,h,half) ----------------
// 256 threads / 8 warps, each warp owns 16 query rows. 2 blocks per (i,h).
// fp16 2-term: Q split (A), K single (B); P split (A), V single (B). ldmatrix B loads.
// smem (uint32): KH[256][20], VTH[32][132] = 37.4KB
#define AKH 0
#define AVH 5120
#define ATOT 9344
__global__ __launch_bounds__(256,2) void k_attn()
{
    extern __shared__ uint32_t sm[];
    uint32_t* KH = sm + AKH;    // [256][20]
    uint32_t* VTH = sm + AVH;   // [32][132]

    const int i = blockIdx.x, h = blockIdx.y, half = blockIdx.z;
    const int tid = threadIdx.x;
    const int lane = tid & 31, wid = tid >> 5;
    const int gid = lane >> 2, tig = lane & 3;
    const int li = lane & 7, gb = lane >> 3;

    // stage K and V^T (pure copies of fp16-packed data)
    {
        const uint4* kH4 = (const uint4*)g_kH;
        for (int idx = tid; idx < 1024; idx += 256){
            int r = idx >> 2, c4 = idx & 3;
            size_t gi = ((size_t)(i*LL + r))*16 + h*4 + c4;
            *(uint4*)(KH + r*20 + c4*4) = kH4[gi];
        }
        const uint4* vH4 = (const uint4*)g_vTH;
        for (int idx = tid; idx < 1024; idx += 256){
            int d = idx >> 5, c4 = idx & 31;
            size_t gi = ((size_t)((i*NHEAD + h)*DHEAD + d))*32 + c4;
            *(uint4*)(VTH + d*132 + c4*4) = vH4[gi];
        }
    }

    // Q fragments: direct pre-split loads (this warp's 16 rows)
    const int j0 = half*128 + wid*16 + gid;
    uint32_t QHf[2][4], QLf[2][4];
    {
        const uint32_t* qH = g_qH + ((size_t)(i*LL + j0))*64 + h*16;
        const uint32_t* qL = g_qL + ((size_t)(i*LL + j0))*64 + h*16;
        #pragma unroll
        for (int ks = 0; ks < 2; ks++){
            QHf[ks][0] = qH[ks*8 + tig];
            QHf[ks][1] = qH[8*64 + ks*8 + tig];
            QHf[ks][2] = qH[ks*8 + tig + 4];
            QHf[ks][3] = qH[8*64 + ks*8 + tig + 4];
            QLf[ks][0] = qL[ks*8 + tig];
            QLf[ks][1] = qL[8*64 + ks*8 + tig];
            QLf[ks][2] = qL[ks*8 + tig + 4];
            QLf[ks][3] = qL[8*64 + ks*8 + tig + 4];
        }
    }
    __syncthreads();

    // ldmatrix per-lane bases (B side):
    const uint32_t kB0 = smaddr(KH)  + ((uint32_t)((gb>>1)*8 + li)*20  + (gb&1)*4) * 4;
    const uint32_t vB0 = smaddr(VTH) + ((uint32_t)((gb>>1)*8 + li)*132 + (gb&1)*4) * 4;

    float lrow[2], O[4][4];
    #pragma unroll
    for (int rr = 0; rr < 2; rr++) lrow[rr] = 0.f;
    #pragma unroll
    for (int nf = 0; nf < 4; nf++)
        #pragma unroll
        for (int q = 0; q < 4; q++) O[nf][q] = 0.f;

    for (int ch = 0; ch < 4; ch++){
        float S[8][4];
        #pragma unroll
        for (int nf = 0; nf < 8; nf++)
            #pragma unroll
            for (int q = 0; q < 4; q++) S[nf][q] = 0.f;

        // S = Q K^T (2-term fp16: Qh*K + Ql*K); log2 units
        #pragma unroll
        for (int ks = 0; ks < 2; ks++){
            #pragma unroll
            for (int np = 0; np < 4; np++){
                uint32_t B[4];
                ldsm4(B, kB0 + (uint32_t)((ch*64 + np*16)*20 + ks*8) * 4);
                #pragma unroll
                for (int c = 0; c < 2; c++){
                    int nf = 2*np + c;
                    mma16816(S[nf], QHf[ks], B[2*c], B[2*c+1]);
                    mma16816(S[nf], QLf[ks], B[2*c], B[2*c+1]);
                }
            }
        }

        // mask (fast path when all bits set) + single-pass exp2
        #pragma unroll
        for (int rr = 0; rr < 2; rr++){
            int j = j0 + rr*8;
            unsigned w0 = g_mask[j*8 + ch*2];
            unsigned w1 = g_mask[j*8 + ch*2 + 1];
            if ((w0 & w1) != 0xFFFFFFFFu){
                #pragma unroll
                for (int nf = 0; nf < 8; nf++){
                    #pragma unroll
                    for (int cc = 0; cc < 2; cc++){
                        int kb = nf*8 + 2*tig + cc;
                        unsigned w = (kb < 32) ? w0 : w1;
                        if (!((w >> (kb & 31)) & 1u)) S[nf][rr*2+cc] = -1e9f;
                    }
                }
            }
            float ls = 0.f;
            #pragma unroll
            for (int nf = 0; nf < 8; nf++){
                float p0 = exp2f(S[nf][rr*2]);
                float p1 = exp2f(S[nf][rr*2+1]);
                S[nf][rr*2] = p0; S[nf][rr*2+1] = p1;
                ls += p0 + p1;
            }
            lrow[rr] += ls;
        }

        // O += P V  (P split fp16 in registers; V single, ldmatrix)
        #pragma unroll
        for (int g = 0; g < 4; g++){
            uint32_t AH[4], AL[4];
            split2h(S[2*g][0],   S[2*g][1],   AH[0], AL[0]);
            split2h(S[2*g][2],   S[2*g][3],   AH[1], AL[1]);
            split2h(S[2*g+1][0], S[2*g+1][1], AH[2], AL[2]);
            split2h(S[2*g+1][2], S[2*g+1][3], AH[3], AL[3]);
            #pragma unroll
            for (int np = 0; np < 2; np++){
                uint32_t B[4];
                ldsm4(B, vB0 + (uint32_t)(np*16*132 + ch*32 + g*8) * 4);
                #pragma unroll
                for (int c = 0; c < 2; c++){
                    int nf = 2*np + c;
                    mma16816(O[nf], AH, B[2*c], B[2*c+1]);
                    mma16816(O[nf], AL, B[2*c], B[2*c+1]);
                }
            }
        }
    }

    // finalize + write (fp16 split for outproj A-operand)
    #pragma unroll
    for (int rr = 0; rr < 2; rr++){
        float l = lrow[rr];
        l += __shfl_xor_sync(0xffffffffu, l, 1);
        l += __shfl_xor_sync(0xffffffffu, l, 2);
        float inv = 1.f / l;
        int j = j0 + rr*8;
        size_t rb = (size_t)(i*LL + j)*64 + h*16;   // head h = pairs h*16..h*16+15
        #pragma unroll
        for (int nf = 0; nf < 4; nf++){
            float o0 = O[nf][rr*2]   * inv;
            float o1 = O[nf][rr*2+1] * inv;
            uint32_t hi, lo; split2h(o0, o1, hi, lo);
            g_attH[rb + nf*4 + tig] = hi;
            g_attL[rb + nf*4 + tig] = lo;
        }
    }
}

// ---------------- kernel 3: out projection + gate ----------------
// 512 threads / 16 warps, 128 rows/block. smem: A hi/lo [128][68] + Wo [128][68] = 104.4KB
__global__ __launch_bounds__(512,1) void k_outproj(const float* __restrict__ bo,
                                                   float* __restrict__ out)
{
    extern __shared__ uint32_t sm[];
    uint32_t* AHs = sm;                 // 128*68
    uint32_t* ALs = sm + 128*WST;
    uint32_t* WH  = sm + 2*128*WST;     // 128*68

    const int row0 = blockIdx.x * 128;
    const int tid = threadIdx.x;
    const int lane = tid & 31, wid = tid >> 5;     // wid 0..15
    const int gid = lane >> 2, tig = lane & 3;
    const int li = lane & 7, gb = lane >> 3;

    // stage activations (pure copy of pre-split fp16 data) + Wo
    {
        const uint4* aH4 = (const uint4*)g_attH;
        const uint4* aL4 = (const uint4*)g_attL;
        for (int idx = tid; idx < 2048; idx += 512){
            int r = idx >> 4, c4 = idx & 15;
            size_t gi = ((size_t)(row0 + r))*16 + c4;
            *(uint4*)(AHs + r*WST + c4*4) = aH4[gi];
            *(uint4*)(ALs + r*WST + c4*4) = aL4[gi];
        }
        const float4* sH = (const float4*)(g_WH + 4*128*WST);
        float4* dH = (float4*)WH;
        for (int idx = tid; idx < 128*WST/4; idx += 512) dH[idx] = sH[idx];
    }
    __syncthreads();

    const int wm = wid >> 2, wn = wid & 3;
    const int m0 = wm*32, n0 = wn*32;

    const uint32_t aOff = ((uint32_t)(m0 + (gb&1)*8 + li)*WST + (gb>>1)*4) * 4;
    const uint32_t aH0 = smaddr(AHs) + aOff;
    const uint32_t aL0 = smaddr(ALs) + aOff;
    const uint32_t bW0 = smaddr(WH) + ((uint32_t)(n0 + (gb>>1)*8 + li)*WST + (gb&1)*4) * 4;

    float C[2][4][4];
    #pragma unroll
    for (int mi=0; mi<2; mi++)
        #pragma unroll
        for (int nf=0; nf<4; nf++)
            #pragma unroll
            for (int q=0; q<4; q++) C[mi][nf][q] = 0.f;

    #pragma unroll
    for (int ks = 0; ks < 8; ks++){
        uint32_t AH[2][4], AL[2][4], B[2][4];
        #pragma unroll
        for (int mi = 0; mi < 2; mi++){
            uint32_t o = (uint32_t)(mi*16*WST + ks*8) * 4;
            ldsm4(AH[mi], aH0 + o);
            ldsm4(AL[mi], aL0 + o);
        }
        #pragma unroll
        for (int np = 0; np < 2; np++)
            ldsm4(B[np], bW0 + (uint32_t)(np*16*WST + ks*8) * 4);
        #pragma unroll
        for (int np = 0; np < 2; np++){
            #pragma unroll
            for (int c = 0; c < 2; c++){
                int nf = 2*np + c;
                #pragma unroll
                for (int mi = 0; mi < 2; mi++){
                    mma16816(C[mi][nf], AH[mi], B[np][2*c], B[np][2*c+1]);
                    mma16816(C[mi][nf], AL[mi], B[np][2*c], B[np][2*c+1]);
                }
            }
        }
    }

    #pragma unroll
    for (int mi = 0; mi < 2; mi++){
        #pragma unroll
        for (int nf = 0; nf < 4; nf++){
            int col = n0 + nf*8 + 2*tig;
            float b0 = bo[col], b1 = bo[col+1];
            int r0 = row0 + m0 + mi*16 + gid;
            size_t a0 = (size_t)r0*DD + col;
            size_t a1 = (size_t)(r0+8)*DD + col;
            uint32_t gp0 = g_gateP[(size_t)r0*64 + (col>>1)];
            uint32_t gp1 = g_gateP[(size_t)(r0+8)*64 + (col>>1)];
            __half2 hg0 = *reinterpret_cast<__half2*>(&gp0);
            __half2 hg1 = *reinterpret_cast<__half2*>(&gp1);
            *(float2*)(out + a0) = make_float2((C[mi][nf][0]+b0)*__half2float(hg0.x),
                                               (C[mi][nf][1]+b1)*__half2float(hg0.y));
            *(float2*)(out + a1) = make_float2((C[mi][nf][2]+b0)*__half2float(hg1.x),
                                               (C[mi][nf][3]+b1)*__half2float(hg1.y));
        }
    }
}

// ---------------- launch ----------------
extern "C" void kernel_launch(void* const* d_in, const int* in_sizes, int n_in,
                              void* d_out, int out_size)
{
    const float* pair = (const float*)d_in[0];
    const int*   mask = (const int*)d_in[1];
    const float* ln_g = (const float*)d_in[2];
    const float* ln_b = (const float*)d_in[3];
    const float* Wq = (const float*)d_in[4];  const float* bq = (const float*)d_in[5];
    const float* Wk = (const float*)d_in[6];  const float* bk = (const float*)d_in[7];
    const float* Wv = (const float*)d_in[8];  const float* bv = (const float*)d_in[9];
    const float* Wo = (const float*)d_in[10]; const float* bo = (const float*)d_in[11];
    const float* Wg = (const float*)d_in[12]; const float* bg = (const float*)d_in[13];
    float* out = (float*)d_out;

    const int smemP = (3*128*WST) * 4;              // 104448
    const int smemA = ATOT * 4;                      // 37376
    cudaFuncSetAttribute(k_lnproj,  cudaFuncAttributeMaxDynamicSharedMemorySize, smemP);
    cudaFuncSetAttribute(k_outproj, cudaFuncAttributeMaxDynamicSharedMemorySize, smemP);
    cudaFuncSetAttribute(k_attn,    cudaFuncAttributeMaxDynamicSharedMemorySize, smemA);

    k_prep<<<5, 256>>>(Wq, Wk, Wv, Wg, Wo);
    k_maskpack<<<1, 256>>>(mask);
    k_lnproj<<<NROWS/128, 512, smemP>>>(pair, ln_g, ln_b, bq, bk, bv, bg);
    dim3 ga(LL, NHEAD, 2);
    k_attn<<<ga, 256, smemA>>>();
    k_outproj<<<NROWS/128, 512, smemP>>>(bo, out);
}

// round 16
// speedup vs baseline: 1.3384x; 1.0914x over previous
#include <cuda_runtime.h>
#include <cuda_fp16.h>
#include <cstdint>
#include <math.h>

#define LL 256
#define DD 128
#define NHEAD 4
#define DHEAD 32
#define NROWS (LL*LL)   // 65536
#define WST 68          // packed-pair row stride (uint32) for smem images

// ---------------- scratch ----------------
__device__ uint32_t g_WH[5*128*WST];          // weights fp16 packed pairs (smem image layout)
__device__ uint32_t g_qH[(size_t)NROWS*64];   // q pre-scaled by log2e/sqrt(32), fp16 split hi
__device__ uint32_t g_qL[(size_t)NROWS*64];   // fp16 split lo
__device__ uint32_t g_kH[(size_t)NROWS*64];   // k single fp16 pairs
__device__ uint32_t g_vTH[(size_t)LL*NHEAD*DHEAD*128];  // v^T single fp16 pairs [i][h][d][j-pair]
__device__ uint32_t g_gateP[(size_t)NROWS*64];// gate packed fp16 pairs
__device__ uint32_t g_attP[(size_t)NROWS*64]; // att single fp16 pairs
__device__ unsigned g_mask[LL*8];

// ---------------- helpers ----------------
__device__ __forceinline__ uint32_t packh(__half a, __half b){
    __half2 t; t.x = a; t.y = b;
    return *reinterpret_cast<uint32_t*>(&t);
}
__device__ __forceinline__ uint32_t pack1h(float x0, float x1){
    return packh(__float2half_rn(x0), __float2half_rn(x1));
}
__device__ __forceinline__ void split2h(float x0, float x1, uint32_t& hi, uint32_t& lo){
    __half h0 = __float2half_rn(x0);
    __half h1 = __float2half_rn(x1);
    __half l0 = __float2half_rn(x0 - __half2float(h0));
    __half l1 = __float2half_rn(x1 - __half2float(h1));
    hi = packh(h0, h1); lo = packh(l0, l1);
}
__device__ __forceinline__ void split1h(float x, __half& h, __half& l){
    h = __float2half_rn(x);
    l = __float2half_rn(x - __half2float(h));
}
__device__ __forceinline__ void mma16816(float* c, const uint32_t* a, uint32_t b0, uint32_t b1){
    asm volatile("mma.sync.aligned.m16n8k16.row.col.f32.f16.f16.f32 "
        "{%0,%1,%2,%3}, {%4,%5,%6,%7}, {%8,%9}, {%0,%1,%2,%3};\n"
        : "+f"(c[0]), "+f"(c[1]), "+f"(c[2]), "+f"(c[3])
        : "r"(a[0]), "r"(a[1]), "r"(a[2]), "r"(a[3]), "r"(b0), "r"(b1));
}
__device__ __forceinline__ uint32_t smaddr(const void* p){
    return (uint32_t)__cvta_generic_to_shared(p);
}
__device__ __forceinline__ void ldsm4(uint32_t* r, uint32_t a){
    asm volatile("ldmatrix.sync.aligned.m8n8.x4.shared.b16 {%0,%1,%2,%3}, [%4];"
        : "=r"(r[0]), "=r"(r[1]), "=r"(r[2]), "=r"(r[3]) : "r"(a));
}

// ---------------- kernel: prep weights (fp16 pairs along d) ----------------
__global__ void k_prep(const float* __restrict__ Wq, const float* __restrict__ Wk,
                       const float* __restrict__ Wv, const float* __restrict__ Wg,
                       const float* __restrict__ Wo)
{
    int m = blockIdx.x;
    const float* W = (m==0)?Wq:(m==1)?Wk:(m==2)?Wv:(m==3)?Wg:Wo;
    uint32_t* H = g_WH + m*128*WST;
    for (int idx = threadIdx.x; idx < 128*WST; idx += blockDim.x){
        int e = idx / WST, p = idx % WST;
        uint32_t hv = 0;
        if (p < 64) hv = pack1h(W[e*DD + 2*p], W[e*DD + 2*p + 1]);
        H[idx] = hv;
    }
}

// ---------------- kernel: pack mask ----------------
__global__ void k_maskpack(const int* __restrict__ mask)
{
    int j = threadIdx.x;
    const int* mrow = mask + (size_t)j*LL;
    #pragma unroll
    for (int w = 0; w < 8; w++){
        unsigned bits = 0;
        #pragma unroll
        for (int b = 0; b < 32; b++) bits |= (mrow[w*32+b] != 0 ? 1u : 0u) << b;
        g_mask[j*8 + w] = bits;
    }
}

// ---------------- kernel 1: LayerNorm + q/k/v/gate projections ----------------
// 256 threads, 64 rows/block. smem: PN hi/lo [64][68] + W [128][68] = 68KB
__global__ __launch_bounds__(256,2) void k_lnproj(
    const float* __restrict__ pair,
    const float* __restrict__ ln_g, const float* __restrict__ ln_b,
    const float* __restrict__ bq, const float* __restrict__ bk,
    const float* __restrict__ bv, const float* __restrict__ bg)
{
    extern __shared__ uint32_t sm[];
    uint32_t* PNH = sm;                 // 64*68
    uint32_t* PNL = sm + 64*WST;
    uint32_t* WH  = sm + 2*64*WST;      // 128*68
    __half* PNHh = (__half*)PNH;
    __half* PNLh = (__half*)PNL;

    const int row0 = blockIdx.x * 64;
    const int tid = threadIdx.x;
    const int lane = tid & 31, wid = tid >> 5;
    const int gid = lane >> 2, tig = lane & 3;
    const int li = lane & 7, gb = lane >> 3;
    const float QSC = 0.17677669529663687f * 1.4426950408889634f;  // (1/sqrt 32)*log2(e)

    // ---- LayerNorm: 8 warps x 8 rows, fp16 split into smem ----
    {
        float lg[4], lb[4];
        #pragma unroll
        for (int t = 0; t < 4; t++){ lg[t] = ln_g[lane + 32*t]; lb[t] = ln_b[lane + 32*t]; }
        for (int rr = 0; rr < 8; rr++){
            int r = wid*8 + rr;
            const float* x = pair + (size_t)(row0 + r)*DD;
            float v[4];
            #pragma unroll
            for (int t = 0; t < 4; t++) v[t] = x[lane + 32*t];
            float s = v[0]+v[1]+v[2]+v[3];
            #pragma unroll
            for (int o = 16; o > 0; o >>= 1) s += __shfl_xor_sync(0xffffffffu, s, o);
            float mu = s * (1.f/128.f);
            float sq = 0.f;
            #pragma unroll
            for (int t = 0; t < 4; t++){ v[t] -= mu; sq += v[t]*v[t]; }
            #pragma unroll
            for (int o = 16; o > 0; o >>= 1) sq += __shfl_xor_sync(0xffffffffu, sq, o);
            float rstd = rsqrtf(sq*(1.f/128.f) + 1e-5f);
            #pragma unroll
            for (int t = 0; t < 4; t++){
                float pn = v[t]*rstd*lg[t] + lb[t];
                __half h, l; split1h(pn, h, l);
                PNHh[r*(2*WST) + lane + 32*t] = h;
                PNLh[r*(2*WST) + lane + 32*t] = l;
            }
        }
    }
    __syncthreads();

    const int wm = wid >> 2, wn = wid & 3;
    const int m0 = wm*32, n0 = wn*32;

    // ldmatrix per-lane bases
    const uint32_t aOff = ((uint32_t)(m0 + (gb&1)*8 + li)*WST + (gb>>1)*4) * 4;
    const uint32_t aH0 = smaddr(PNH) + aOff;
    const uint32_t aL0 = smaddr(PNL) + aOff;
    const uint32_t bW0 = smaddr(WH) + ((uint32_t)(n0 + (gb>>1)*8 + li)*WST + (gb&1)*4) * 4;

    for (int p = 0; p < 4; p++){
        const bool full = (p < 2);   // v and gate projections: 1-term
        // stage weights (single fp16 image)
        {
            const float4* sH = (const float4*)(g_WH + p*128*WST);
            float4* dH = (float4*)WH;
            for (int idx = tid; idx < 128*WST/4; idx += 256) dH[idx] = sH[idx];
        }
        __syncthreads();

        float C[2][4][4];
        #pragma unroll
        for (int mi=0; mi<2; mi++)
            #pragma unroll
            for (int nf=0; nf<4; nf++)
                #pragma unroll
                for (int q=0; q<4; q++) C[mi][nf][q] = 0.f;

        #pragma unroll
        for (int ks = 0; ks < 8; ks++){
            uint32_t AH[2][4], AL[2][4], B[2][4];
            #pragma unroll
            for (int mi = 0; mi < 2; mi++){
                uint32_t o = (uint32_t)(mi*16*WST + ks*8) * 4;
                ldsm4(AH[mi], aH0 + o);
                if (full) ldsm4(AL[mi], aL0 + o);
            }
            #pragma unroll
            for (int np = 0; np < 2; np++)
                ldsm4(B[np], bW0 + (uint32_t)(np*16*WST + ks*8) * 4);
            #pragma unroll
            for (int np = 0; np < 2; np++){
                #pragma unroll
                for (int c = 0; c < 2; c++){
                    int nf = 2*np + c;
                    #pragma unroll
                    for (int mi = 0; mi < 2; mi++){
                        mma16816(C[mi][nf], AH[mi], B[np][2*c], B[np][2*c+1]);
                        if (full) mma16816(C[mi][nf], AL[mi], B[np][2*c], B[np][2*c+1]);
                    }
                }
            }
        }

        if (p == 2) __syncthreads();   // all warps done reading WH before vtile overlay

        const float* bias = (p==0)?bq:(p==1)?bk:(p==2)?bv:bg;
        #pragma unroll
        for (int mi = 0; mi < 2; mi++){
            #pragma unroll
            for (int nf = 0; nf < 4; nf++){
                int col = n0 + nf*8 + 2*tig;
                float b0 = bias[col], b1 = bias[col+1];
                float v00 = C[mi][nf][0] + b0, v01 = C[mi][nf][1] + b1;
                float v10 = C[mi][nf][2] + b0, v11 = C[mi][nf][3] + b1;
                int rl = m0 + mi*16 + gid;        // local row 0..63
                int r0 = row0 + rl;
                if (p == 0){
                    v00 *= QSC; v01 *= QSC; v10 *= QSC; v11 *= QSC;
                    uint32_t hi, lo;
                    split2h(v00, v01, hi, lo);
                    g_qH[(size_t)r0*64 + (col>>1)] = hi; g_qL[(size_t)r0*64 + (col>>1)] = lo;
                    split2h(v10, v11, hi, lo);
                    g_qH[(size_t)(r0+8)*64 + (col>>1)] = hi; g_qL[(size_t)(r0+8)*64 + (col>>1)] = lo;
                } else if (p == 1){
                    g_kH[(size_t)r0*64 + (col>>1)]     = pack1h(v00, v01);
                    g_kH[(size_t)(r0+8)*64 + (col>>1)] = pack1h(v10, v11);
                } else if (p == 2){
                    float* vt = (float*)WH;       // [64][131] overlay
                    vt[rl*131 + col] = v00; vt[rl*131 + col + 1] = v01;
                    vt[(rl+8)*131 + col] = v10; vt[(rl+8)*131 + col + 1] = v11;
                } else {
                    v00 = 1.f/(1.f+__expf(-v00)); v01 = 1.f/(1.f+__expf(-v01));
                    v10 = 1.f/(1.f+__expf(-v10)); v11 = 1.f/(1.f+__expf(-v11));
                    g_gateP[(size_t)r0*64 + (col>>1)]     = pack1h(v00, v01);
                    g_gateP[(size_t)(r0+8)*64 + (col>>1)] = pack1h(v10, v11);
                }
            }
        }

        if (p == 2){
            __syncthreads();
            // transpose v tile -> g_vTH (single fp16) (block covers j0..j0+63 of row i)
            const int i_ = row0 >> 8, j0_ = row0 & 255;
            const float* vt = (const float*)WH;
            for (int idx = tid; idx < 4096; idx += 256){
                int h_ = idx >> 10;
                int rem = idx & 1023;
                int d_ = rem >> 5;
                int jp = rem & 31;
                float v0 = vt[(jp*2)*131 + h_*32 + d_];
                float v1 = vt[(jp*2+1)*131 + h_*32 + d_];
                size_t o = ((size_t)((i_*NHEAD + h_)*DHEAD + d_))*128 + (j0_>>1) + jp;
                g_vTH[o] = pack1h(v0, v1);
            }
        }
        __syncthreads();
    }
}

// ---------------- kernel 2: attention per (i,h,half) ----------------
// 256 threads / 8 warps, each warp owns 16 query rows. 2 blocks per (i,h).
// Q split 2-term vs K single; P single vs V single. ldmatrix B loads.
// smem (uint32): KH[256][20], VTH[32][132] = 37.4KB
#define AKH 0
#define AVH 5120
#define ATOT 9344
__global__ __launch_bounds__(256,2) void k_attn()
{
    extern __shared__ uint32_t sm[];
    uint32_t* KH = sm + AKH;    // [256][20]
    uint32_t* VTH = sm + AVH;   // [32][132]

    const int i = blockIdx.x, h = blockIdx.y, half = blockIdx.z;
    const int tid = threadIdx.x;
    const int lane = tid & 31, wid = tid >> 5;
    const int gid = lane >> 2, tig = lane & 3;
    const int li = lane & 7, gb = lane >> 3;

    // stage K and V^T (pure copies of fp16-packed data)
    {
        const uint4* kH4 = (const uint4*)g_kH;
        for (int idx = tid; idx < 1024; idx += 256){
            int r = idx >> 2, c4 = idx & 3;
            size_t gi = ((size_t)(i*LL + r))*16 + h*4 + c4;
            *(uint4*)(KH + r*20 + c4*4) = kH4[gi];
        }
        const uint4* vH4 = (const uint4*)g_vTH;
        for (int idx = tid; idx < 1024; idx += 256){
            int d = idx >> 5, c4 = idx & 31;
            size_t gi = ((size_t)((i*NHEAD + h)*DHEAD + d))*32 + c4;
            *(uint4*)(VTH + d*132 + c4*4) = vH4[gi];
        }
    }

    // Q fragments: direct pre-split loads (this warp's 16 rows)
    const int j0 = half*128 + wid*16 + gid;
    uint32_t QHf[2][4], QLf[2][4];
    {
        const uint32_t* qH = g_qH + ((size_t)(i*LL + j0))*64 + h*16;
        const uint32_t* qL = g_qL + ((size_t)(i*LL + j0))*64 + h*16;
        #pragma unroll
        for (int ks = 0; ks < 2; ks++){
            QHf[ks][0] = qH[ks*8 + tig];
            QHf[ks][1] = qH[8*64 + ks*8 + tig];
            QHf[ks][2] = qH[ks*8 + tig + 4];
            QHf[ks][3] = qH[8*64 + ks*8 + tig + 4];
            QLf[ks][0] = qL[ks*8 + tig];
            QLf[ks][1] = qL[8*64 + ks*8 + tig];
            QLf[ks][2] = qL[ks*8 + tig + 4];
            QLf[ks][3] = qL[8*64 + ks*8 + tig + 4];
        }
    }
    __syncthreads();

    // ldmatrix per-lane bases (B side):
    const uint32_t kB0 = smaddr(KH)  + ((uint32_t)((gb>>1)*8 + li)*20  + (gb&1)*4) * 4;
    const uint32_t vB0 = smaddr(VTH) + ((uint32_t)((gb>>1)*8 + li)*132 + (gb&1)*4) * 4;

    float lrow[2], O[4][4];
    #pragma unroll
    for (int rr = 0; rr < 2; rr++) lrow[rr] = 0.f;
    #pragma unroll
    for (int nf = 0; nf < 4; nf++)
        #pragma unroll
        for (int q = 0; q < 4; q++) O[nf][q] = 0.f;

    for (int ch = 0; ch < 4; ch++){
        float S[8][4];
        #pragma unroll
        for (int nf = 0; nf < 8; nf++)
            #pragma unroll
            for (int q = 0; q < 4; q++) S[nf][q] = 0.f;

        // S = Q K^T (2-term fp16: Qh*K + Ql*K); log2 units
        #pragma unroll
        for (int ks = 0; ks < 2; ks++){
            #pragma unroll
            for (int np = 0; np < 4; np++){
                uint32_t B[4];
                ldsm4(B, kB0 + (uint32_t)((ch*64 + np*16)*20 + ks*8) * 4);
                #pragma unroll
                for (int c = 0; c < 2; c++){
                    int nf = 2*np + c;
                    mma16816(S[nf], QHf[ks], B[2*c], B[2*c+1]);
                    mma16816(S[nf], QLf[ks], B[2*c], B[2*c+1]);
                }
            }
        }

        // mask (fast path when all bits set) + single-pass exp2
        #pragma unroll
        for (int rr = 0; rr < 2; rr++){
            int j = j0 + rr*8;
            unsigned w0 = g_mask[j*8 + ch*2];
            unsigned w1 = g_mask[j*8 + ch*2 + 1];
            if ((w0 & w1) != 0xFFFFFFFFu){
                #pragma unroll
                for (int nf = 0; nf < 8; nf++){
                    #pragma unroll
                    for (int cc = 0; cc < 2; cc++){
                        int kb = nf*8 + 2*tig + cc;
                        unsigned w = (kb < 32) ? w0 : w1;
                        if (!((w >> (kb & 31)) & 1u)) S[nf][rr*2+cc] = -1e9f;
                    }
                }
            }
            float ls = 0.f;
            #pragma unroll
            for (int nf = 0; nf < 8; nf++){
                float p0 = exp2f(S[nf][rr*2]);
                float p1 = exp2f(S[nf][rr*2+1]);
                S[nf][rr*2] = p0; S[nf][rr*2+1] = p1;
                ls += p0 + p1;
            }
            lrow[rr] += ls;
        }

        // O += P V  (P single fp16 in registers; V single, ldmatrix)
        #pragma unroll
        for (int g = 0; g < 4; g++){
            uint32_t AP[4];
            AP[0] = pack1h(S[2*g][0],   S[2*g][1]);
            AP[1] = pack1h(S[2*g][2],   S[2*g][3]);
            AP[2] = pack1h(S[2*g+1][0], S[2*g+1][1]);
            AP[3] = pack1h(S[2*g+1][2], S[2*g+1][3]);
            #pragma unroll
            for (int np = 0; np < 2; np++){
                uint32_t B[4];
                ldsm4(B, vB0 + (uint32_t)(np*16*132 + ch*32 + g*8) * 4);
                #pragma unroll
                for (int c = 0; c < 2; c++){
                    int nf = 2*np + c;
                    mma16816(O[nf], AP, B[2*c], B[2*c+1]);
                }
            }
        }
    }

    // finalize + write (single fp16 for outproj A-operand)
    #pragma unroll
    for (int rr = 0; rr < 2; rr++){
        float l = lrow[rr];
        l += __shfl_xor_sync(0xffffffffu, l, 1);
        l += __shfl_xor_sync(0xffffffffu, l, 2);
        float inv = 1.f / l;
        int j = j0 + rr*8;
        size_t rb = (size_t)(i*LL + j)*64 + h*16;   // head h = pairs h*16..h*16+15
        #pragma unroll
        for (int nf = 0; nf < 4; nf++){
            float o0 = O[nf][rr*2]   * inv;
            float o1 = O[nf][rr*2+1] * inv;
            g_attP[rb + nf*4 + tig] = pack1h(o0, o1);
        }
    }
}

// ---------------- kernel 3: out projection + gate ----------------
// smem: att [64][68] + Wo [128][68] = 52.2KB; A single-term.
__global__ __launch_bounds__(256,2) void k_outproj(const float* __restrict__ bo,
                                                   float* __restrict__ out)
{
    extern __shared__ uint32_t sm[];
    uint32_t* AHs = sm;                 // 64*68
    uint32_t* WH  = sm + 64*WST;        // 128*68

    const int row0 = blockIdx.x * 64;
    const int tid = threadIdx.x;
    const int lane = tid & 31, wid = tid >> 5;
    const int gid = lane >> 2, tig = lane & 3;
    const int li = lane & 7, gb = lane >> 3;

    // stage activations (pure copy) + Wo
    {
        const uint4* aH4 = (const uint4*)g_attP;
        for (int idx = tid; idx < 1024; idx += 256){
            int r = idx >> 4, c4 = idx & 15;
            size_t gi = ((size_t)(row0 + r))*16 + c4;
            *(uint4*)(AHs + r*WST + c4*4) = aH4[gi];
        }
        const float4* sH = (const float4*)(g_WH + 4*128*WST);
        float4* dH = (float4*)WH;
        for (int idx = tid; idx < 128*WST/4; idx += 256) dH[idx] = sH[idx];
    }
    __syncthreads();

    const int wm = wid >> 2, wn = wid & 3;
    const int m0 = wm*32, n0 = wn*32;

    const uint32_t aH0 = smaddr(AHs) + ((uint32_t)(m0 + (gb&1)*8 + li)*WST + (gb>>1)*4) * 4;
    const uint32_t bW0 = smaddr(WH) + ((uint32_t)(n0 + (gb>>1)*8 + li)*WST + (gb&1)*4) * 4;

    float C[2][4][4];
    #pragma unroll
    for (int mi=0; mi<2; mi++)
        #pragma unroll
        for (int nf=0; nf<4; nf++)
            #pragma unroll
            for (int q=0; q<4; q++) C[mi][nf][q] = 0.f;

    #pragma unroll
    for (int ks = 0; ks < 8; ks++){
        uint32_t AH[2][4], B[2][4];
        #pragma unroll
        for (int mi = 0; mi < 2; mi++)
            ldsm4(AH[mi], aH0 + (uint32_t)(mi*16*WST + ks*8) * 4);
        #pragma unroll
        for (int np = 0; np < 2; np++)
            ldsm4(B[np], bW0 + (uint32_t)(np*16*WST + ks*8) * 4);
        #pragma unroll
        for (int np = 0; np < 2; np++){
            #pragma unroll
            for (int c = 0; c < 2; c++){
                int nf = 2*np + c;
                #pragma unroll
                for (int mi = 0; mi < 2; mi++)
                    mma16816(C[mi][nf], AH[mi], B[np][2*c], B[np][2*c+1]);
            }
        }
    }

    #pragma unroll
    for (int mi = 0; mi < 2; mi++){
        #pragma unroll
        for (int nf = 0; nf < 4; nf++){
            int col = n0 + nf*8 + 2*tig;
            float b0 = bo[col], b1 = bo[col+1];
            int r0 = row0 + m0 + mi*16 + gid;
            size_t a0 = (size_t)r0*DD + col;
            size_t a1 = (size_t)(r0+8)*DD + col;
            uint32_t gp0 = g_gateP[(size_t)r0*64 + (col>>1)];
            uint32_t gp1 = g_gateP[(size_t)(r0+8)*64 + (col>>1)];
            __half2 hg0 = *reinterpret_cast<__half2*>(&gp0);
            __half2 hg1 = *reinterpret_cast<__half2*>(&gp1);
            *(float2*)(out + a0) = make_float2((C[mi][nf][0]+b0)*__half2float(hg0.x),
                                               (C[mi][nf][1]+b1)*__half2float(hg0.y));
            *(float2*)(out + a1) = make_float2((C[mi][nf][2]+b0)*__half2float(hg1.x),
                                               (C[mi][nf][3]+b1)*__half2float(hg1.y));
        }
    }
}

// ---------------- launch ----------------
extern "C" void kernel_launch(void* const* d_in, const int* in_sizes, int n_in,
                              void* d_out, int out_size)
{
    const float* pair = (const float*)d_in[0];
    const int*   mask = (const int*)d_in[1];
    const float* ln_g = (const float*)d_in[2];
    const float* ln_b = (const float*)d_in[3];
    const float* Wq = (const float*)d_in[4];  const float* bq = (const float*)d_in[5];
    const float* Wk = (const float*)d_in[6];  const float* bk = (const float*)d_in[7];
    const float* Wv = (const float*)d_in[8];  const float* bv = (const float*)d_in[9];
    const float* Wo = (const float*)d_in[10]; const float* bo = (const float*)d_in[11];
    const float* Wg = (const float*)d_in[12]; const float* bg = (const float*)d_in[13];
    float* out = (float*)d_out;

    const int smemP = (2*64*WST + 128*WST) * 4;     // 69632
    const int smemO = (64*WST + 128*WST) * 4;       // 52224
    const int smemA = ATOT * 4;                      // 37376
    cudaFuncSetAttribute(k_lnproj,  cudaFuncAttributeMaxDynamicSharedMemorySize, smemP);
    cudaFuncSetAttribute(k_outproj, cudaFuncAttributeMaxDynamicSharedMemorySize, smemO);
    cudaFuncSetAttribute(k_attn,    cudaFuncAttributeMaxDynamicSharedMemorySize, smemA);

    k_prep<<<5, 256>>>(Wq, Wk, Wv, Wg, Wo);
    k_maskpack<<<1, 256>>>(mask);
    k_lnproj<<<NROWS/64, 256, smemP>>>(pair, ln_g, ln_b, bq, bk, bv, bg);
    dim3 ga(LL, NHEAD, 2);
    k_attn<<<ga, 256, smemA>>>();
    k_outproj<<<NROWS/64, 256, smemO>>>(bo, out);
}